// round 4
// baseline (speedup 1.0000x reference)
#include <cuda_runtime.h>
#include <cuda_bf16.h>

// Problem constants
// T=1024, B=4, E=512, H=8, HD=64, BH=32
// inputs: query[T,B,E], dist[B,T,T,H], in_proj_weight[3E,E], in_proj_bias[3E],
//         out_proj_weight[E,E], out_proj_bias[E]
// output: [T,B,E] float32

namespace {
constexpr int cT  = 1024;
constexpr int cB  = 4;
constexpr int cE  = 512;
constexpr int cH  = 8;
constexpr int cHD = 64;
constexpr int cBH = cB * cH;   // 32
}

// Scratch (no allocation allowed -> device globals)
__device__ float g_q[cBH * cT * cHD];                 // 8 MB, pre-scaled by 1/sqrt(HD)
__device__ float g_k[cBH * cT * cHD];                 // 8 MB
__device__ float g_v[cBH * cT * cHD];                 // 8 MB
__device__ float g_sc[(size_t)cBH * cT * cT];         // 128 MiB scores -> probs (in place)
__device__ float g_ctx[cT * cB * cE];                 // 8 MB attention output in [T,B,E]

// ---------------------------------------------------------------------------
// Kernel 1: in-projection GEMM. M=4096 (t*B+b), N=1536, K=512 (NT, both K-major)
// Epilogue scatters into q/k/v head layout [BH][T][HD]; q scaled by 0.125.
// ---------------------------------------------------------------------------
__global__ __launch_bounds__(256) void k_inproj(const float* __restrict__ A,
                                                const float* __restrict__ W,
                                                const float* __restrict__ bias) {
    __shared__ float As[8][128];
    __shared__ float Bs[8][128];
    const int tid = threadIdx.x;
    const int tx = tid & 15, ty = tid >> 4;
    const int m0 = blockIdx.y * 128, n0 = blockIdx.x * 128;
    const int lrow = tid >> 1, lcol = (tid & 1) << 2;

    float acc[8][8];
#pragma unroll
    for (int i = 0; i < 8; i++)
#pragma unroll
        for (int j = 0; j < 8; j++) acc[i][j] = 0.f;

    const float* aptr = A + (m0 + lrow) * 512 + lcol;
    const float* bptr = W + (n0 + lrow) * 512 + lcol;

    for (int k0 = 0; k0 < 512; k0 += 8) {
        float4 av = *reinterpret_cast<const float4*>(aptr + k0);
        float4 bv = *reinterpret_cast<const float4*>(bptr + k0);
        As[lcol + 0][lrow] = av.x; As[lcol + 1][lrow] = av.y;
        As[lcol + 2][lrow] = av.z; As[lcol + 3][lrow] = av.w;
        Bs[lcol + 0][lrow] = bv.x; Bs[lcol + 1][lrow] = bv.y;
        Bs[lcol + 2][lrow] = bv.z; Bs[lcol + 3][lrow] = bv.w;
        __syncthreads();
#pragma unroll
        for (int kk = 0; kk < 8; kk++) {
            float a[8], bb[8];
#pragma unroll
            for (int i = 0; i < 8; i++) a[i] = As[kk][ty * 8 + i];
#pragma unroll
            for (int j = 0; j < 8; j++) bb[j] = Bs[kk][tx * 8 + j];
#pragma unroll
            for (int i = 0; i < 8; i++)
#pragma unroll
                for (int j = 0; j < 8; j++) acc[i][j] = fmaf(a[i], bb[j], acc[i][j]);
        }
        __syncthreads();
    }

#pragma unroll
    for (int i = 0; i < 8; i++) {
        const int r = m0 + ty * 8 + i;
        const int t = r >> 2, b = r & 3;
#pragma unroll
        for (int j = 0; j < 8; j++) {
            const int n = n0 + tx * 8 + j;
            float v = acc[i][j] + bias[n];
            const int sec = n >> 9;
            const int e = n & 511;
            const int h = e >> 6, hd = e & 63;
            const int dst = ((b * cH + h) * cT + t) * cHD + hd;
            if (sec == 0)      g_q[dst] = v * 0.125f;
            else if (sec == 1) g_k[dst] = v;
            else               g_v[dst] = v;
        }
    }
}

// ---------------------------------------------------------------------------
// Kernel 2: batched QK^T. Per bh: M=N=1024, K=64 (NT). scores -> g_sc.
// ---------------------------------------------------------------------------
__global__ __launch_bounds__(256) void k_qk() {
    __shared__ float As[8][128];
    __shared__ float Bs[8][128];
    const int tid = threadIdx.x;
    const int tx = tid & 15, ty = tid >> 4;
    const int bh = blockIdx.z;
    const int m0 = blockIdx.y * 128, n0 = blockIdx.x * 128;
    const float* A  = g_q + bh * cT * cHD;
    const float* Bm = g_k + bh * cT * cHD;
    const int lrow = tid >> 1, lcol = (tid & 1) << 2;

    float acc[8][8];
#pragma unroll
    for (int i = 0; i < 8; i++)
#pragma unroll
        for (int j = 0; j < 8; j++) acc[i][j] = 0.f;

    for (int k0 = 0; k0 < 64; k0 += 8) {
        float4 av = *reinterpret_cast<const float4*>(A  + (m0 + lrow) * 64 + k0 + lcol);
        float4 bv = *reinterpret_cast<const float4*>(Bm + (n0 + lrow) * 64 + k0 + lcol);
        As[lcol + 0][lrow] = av.x; As[lcol + 1][lrow] = av.y;
        As[lcol + 2][lrow] = av.z; As[lcol + 3][lrow] = av.w;
        Bs[lcol + 0][lrow] = bv.x; Bs[lcol + 1][lrow] = bv.y;
        Bs[lcol + 2][lrow] = bv.z; Bs[lcol + 3][lrow] = bv.w;
        __syncthreads();
#pragma unroll
        for (int kk = 0; kk < 8; kk++) {
            float a[8], bb[8];
#pragma unroll
            for (int i = 0; i < 8; i++) a[i] = As[kk][ty * 8 + i];
#pragma unroll
            for (int j = 0; j < 8; j++) bb[j] = Bs[kk][tx * 8 + j];
#pragma unroll
            for (int i = 0; i < 8; i++)
#pragma unroll
                for (int j = 0; j < 8; j++) acc[i][j] = fmaf(a[i], bb[j], acc[i][j]);
        }
        __syncthreads();
    }

    float* C = g_sc + ((size_t)bh * cT + m0) * cT + n0;
#pragma unroll
    for (int i = 0; i < 8; i++) {
        const int row = ty * 8 + i;
        float* dst = C + (size_t)row * cT + tx * 8;
        *reinterpret_cast<float4*>(dst)     = make_float4(acc[i][0], acc[i][1], acc[i][2], acc[i][3]);
        *reinterpret_cast<float4*>(dst + 4) = make_float4(acc[i][4], acc[i][5], acc[i][6], acc[i][7]);
    }
}

// ---------------------------------------------------------------------------
// Kernel 3: bias + softmax, in place on g_sc. Block = (t, b), loops h=0..7.
// dist row [s*8+h] is contiguous 32KB; h=0 pulls every sector once, h>0 hit L1.
// ---------------------------------------------------------------------------
__global__ __launch_bounds__(256) void k_softmax(const float* __restrict__ dist) {
    const int t = blockIdx.x, b = blockIdx.y;
    const int tid = threadIdx.x;
    const int lane = tid & 31, wid = tid >> 5;
    __shared__ float red[8];
    const float* drow = dist + ((size_t)b * cT + t) * cT * cH;

    for (int h = 0; h < cH; h++) {
        float* srow = g_sc + ((size_t)(b * cH + h) * cT + t) * cT;
        float x[4];
        float m = -1e30f;
#pragma unroll
        for (int q = 0; q < 4; q++) {
            const int s = tid + q * 256;
            x[q] = srow[s] + drow[s * cH + h];
            m = fmaxf(m, x[q]);
        }
#pragma unroll
        for (int o = 16; o; o >>= 1) m = fmaxf(m, __shfl_xor_sync(0xffffffffu, m, o));
        if (lane == 0) red[wid] = m;
        __syncthreads();
        m = red[0];
#pragma unroll
        for (int w = 1; w < 8; w++) m = fmaxf(m, red[w]);

        float sum = 0.f;
#pragma unroll
        for (int q = 0; q < 4; q++) { x[q] = __expf(x[q] - m); sum += x[q]; }
#pragma unroll
        for (int o = 16; o; o >>= 1) sum += __shfl_xor_sync(0xffffffffu, sum, o);
        __syncthreads();                 // red reuse
        if (lane == 0) red[wid] = sum;
        __syncthreads();
        sum = 0.f;
#pragma unroll
        for (int w = 0; w < 8; w++) sum += red[w];
        const float inv = 1.0f / sum;
#pragma unroll
        for (int q = 0; q < 4; q++) srow[tid + q * 256] = x[q] * inv;
        __syncthreads();                 // red reuse next h
    }
}

// ---------------------------------------------------------------------------
// Kernel 4: batched PV. Per bh: M=1024 (t), N=64 (hd), K=1024 (s) (NN).
// Epilogue writes straight into g_ctx[t, b, h*64+hd].
// ---------------------------------------------------------------------------
__global__ __launch_bounds__(256) void k_pv() {
    __shared__ float As[8][128];
    __shared__ float Bs[8][64];
    const int tid = threadIdx.x;
    const int tx = tid & 15, ty = tid >> 4;
    const int bh = blockIdx.z;
    const int m0 = blockIdx.y * 128;
    const float* A = g_sc + (size_t)bh * cT * cT;
    const float* V = g_v + bh * cT * cHD;
    const int arow = tid >> 1, acol = (tid & 1) << 2;
    const int bk = tid >> 5, bn = (tid & 31) << 1;

    float acc[8][4];
#pragma unroll
    for (int i = 0; i < 8; i++)
#pragma unroll
        for (int j = 0; j < 4; j++) acc[i][j] = 0.f;

    for (int k0 = 0; k0 < cT; k0 += 8) {
        float4 av = *reinterpret_cast<const float4*>(A + (size_t)(m0 + arow) * cT + k0 + acol);
        float2 bv = *reinterpret_cast<const float2*>(V + (k0 + bk) * cHD + bn);
        As[acol + 0][arow] = av.x; As[acol + 1][arow] = av.y;
        As[acol + 2][arow] = av.z; As[acol + 3][arow] = av.w;
        Bs[bk][bn] = bv.x; Bs[bk][bn + 1] = bv.y;
        __syncthreads();
#pragma unroll
        for (int kk = 0; kk < 8; kk++) {
            float a[8], bb[4];
#pragma unroll
            for (int i = 0; i < 8; i++) a[i] = As[kk][ty * 8 + i];
#pragma unroll
            for (int j = 0; j < 4; j++) bb[j] = Bs[kk][tx * 4 + j];
#pragma unroll
            for (int i = 0; i < 8; i++)
#pragma unroll
                for (int j = 0; j < 4; j++) acc[i][j] = fmaf(a[i], bb[j], acc[i][j]);
        }
        __syncthreads();
    }

    const int b = bh >> 3, h = bh & 7;
#pragma unroll
    for (int i = 0; i < 8; i++) {
        const int t = m0 + ty * 8 + i;
        float* dst = g_ctx + (t * cB + b) * cE + h * cHD + tx * 4;
        *reinterpret_cast<float4*>(dst) = make_float4(acc[i][0], acc[i][1], acc[i][2], acc[i][3]);
    }
}

// ---------------------------------------------------------------------------
// Kernel 5: out-projection GEMM. M=4096, N=512, K=512 (NT), +bias -> d_out.
// ---------------------------------------------------------------------------
__global__ __launch_bounds__(256) void k_outproj(const float* __restrict__ W,
                                                 const float* __restrict__ bias,
                                                 float* __restrict__ out) {
    __shared__ float As[8][128];
    __shared__ float Bs[8][128];
    const int tid = threadIdx.x;
    const int tx = tid & 15, ty = tid >> 4;
    const int m0 = blockIdx.y * 128, n0 = blockIdx.x * 128;
    const int lrow = tid >> 1, lcol = (tid & 1) << 2;

    float acc[8][8];
#pragma unroll
    for (int i = 0; i < 8; i++)
#pragma unroll
        for (int j = 0; j < 8; j++) acc[i][j] = 0.f;

    const float* aptr = g_ctx + (m0 + lrow) * 512 + lcol;
    const float* bptr = W + (n0 + lrow) * 512 + lcol;

    for (int k0 = 0; k0 < 512; k0 += 8) {
        float4 av = *reinterpret_cast<const float4*>(aptr + k0);
        float4 bv = *reinterpret_cast<const float4*>(bptr + k0);
        As[lcol + 0][lrow] = av.x; As[lcol + 1][lrow] = av.y;
        As[lcol + 2][lrow] = av.z; As[lcol + 3][lrow] = av.w;
        Bs[lcol + 0][lrow] = bv.x; Bs[lcol + 1][lrow] = bv.y;
        Bs[lcol + 2][lrow] = bv.z; Bs[lcol + 3][lrow] = bv.w;
        __syncthreads();
#pragma unroll
        for (int kk = 0; kk < 8; kk++) {
            float a[8], bb[8];
#pragma unroll
            for (int i = 0; i < 8; i++) a[i] = As[kk][ty * 8 + i];
#pragma unroll
            for (int j = 0; j < 8; j++) bb[j] = Bs[kk][tx * 8 + j];
#pragma unroll
            for (int i = 0; i < 8; i++)
#pragma unroll
                for (int j = 0; j < 8; j++) acc[i][j] = fmaf(a[i], bb[j], acc[i][j]);
        }
        __syncthreads();
    }

#pragma unroll
    for (int i = 0; i < 8; i++) {
        const int r = m0 + ty * 8 + i;
#pragma unroll
        for (int j = 0; j < 8; j++) {
            const int n = n0 + tx * 8 + j;
            out[r * 512 + n] = acc[i][j] + bias[n];
        }
    }
}

// ---------------------------------------------------------------------------
extern "C" void kernel_launch(void* const* d_in, const int* in_sizes, int n_in,
                              void* d_out, int out_size) {
    const float* query = (const float*)d_in[0];
    const float* dist  = (const float*)d_in[1];
    const float* w_in  = (const float*)d_in[2];
    const float* b_in  = (const float*)d_in[3];
    const float* w_out = (const float*)d_in[4];
    const float* b_out = (const float*)d_in[5];
    float* out = (float*)d_out;

    k_inproj <<<dim3(1536 / 128, 4096 / 128), 256>>>(query, w_in, b_in);
    k_qk     <<<dim3(cT / 128, cT / 128, cBH), 256>>>();
    k_softmax<<<dim3(cT, cB), 256>>>(dist);
    k_pv     <<<dim3(1, cT / 128, cBH), 256>>>();
    k_outproj<<<dim3(512 / 128, 4096 / 128), 256>>>(w_out, b_out, out);
}